// round 15
// baseline (speedup 1.0000x reference)
#include <cuda_runtime.h>

#define FULL_MASK 0xffffffffu

// out[j] = x[j - offset] for 0 <= j-offset < n else 0, offset from device scalars.
// Warp tile: 128 consecutive output vectors per warp; thread handles k=0..3 at
// lane-contiguous addresses (full coalescing, MLP=4 front-batched aligned loads).
// Misalignment r = offset & 3 fixed via minimal warp shuffles of the needed
// prev-vector words. n % 4 == 0 so whole-vector zero predication is exact.
//
// Best-measured configuration: ~74.8us kernel = GB300 mixed read+write
// HBM/LTS ceiling (verified vs MLP=8, persistent, TMA-bulk, guard-free,
// copy-engine — all neutral or worse). threads=1024 minimizes block count;
// per-warp code identical to the 256/512-thread variants.

__global__ void __launch_bounds__(1024)
shift_warptile(const float4* __restrict__ x4,
               const float*  __restrict__ xs,
               const float*  __restrict__ w_row,
               const float*  __restrict__ w_col,
               int row_length, int n,
               float4* __restrict__ out4)
{
    const int nv = n >> 2;
    const int offset = (int)(w_row[0] + (float)row_length * w_col[0]);
    const int r = offset & 3;
    const int m = (offset - r) >> 2;          // floor(offset/4)

    const int warp_id = (blockIdx.x * blockDim.x + threadIdx.x) >> 5;
    const int lane    = threadIdx.x & 31;
    const int wbase   = warp_id << 7;         // 128 vectors per warp

    // Front-batched independent aligned loads (MLP = 4).
    float4 v[4];
    int g0 = wbase + lane;
#pragma unroll
    for (int k = 0; k < 4; k++) {
        const int g  = g0 + (k << 5);
        const int sv = g - m;
        float4 t = make_float4(0.f, 0.f, 0.f, 0.f);
        if (g < nv && sv >= 0 && sv < nv) t = __ldcs(x4 + sv);
        v[k] = t;
    }

    if (r == 0) {
#pragma unroll
        for (int k = 0; k < 4; k++) {
            const int g = g0 + (k << 5);
            if (g < nv) __stcs(out4 + g, v[k]);
        }
        return;
    }

    // Extra boundary words for lane 0, k = 0: words (4-r..3) of vector wbase-m-1.
    float e_y = 0.f, e_z = 0.f, e_w = 0.f;
    if (lane == 0) {
        const int ebase = 4 * (wbase - m) - 4;
        if (r >= 3) { int i = ebase + 1; if (i >= 0 && i < n) e_y = __ldcs(xs + i); }
        if (r >= 2) { int i = ebase + 2; if (i >= 0 && i < n) e_z = __ldcs(xs + i); }
        /* r>=1 */ { int i = ebase + 3; if (i >= 0 && i < n) e_w = __ldcs(xs + i); }
    }

    // prev-word fetch: value of component from vector (g-m-1) =
    //   lane>0 : lane-1's v[k];  lane0,k>0 : lane31's v[k-1];  lane0,k0 : e_*
#define PREVW(comp, k, evar, dst)                                              \
    do {                                                                       \
        float _up  = __shfl_up_sync(FULL_MASK, v[k].comp, 1);                  \
        float _b31 = __shfl_sync(FULL_MASK, (k) > 0 ? v[(k)>0?(k)-1:0].comp    \
                                                    : 0.f, 31);                \
        dst = (lane == 0) ? ((k) > 0 ? _b31 : (evar)) : _up;                   \
    } while (0)

#pragma unroll
    for (int k = 0; k < 4; k++) {
        float pw, pz, py;
        PREVW(w, k, e_w, pw);
        float4 o;
        if (r == 1) {
            o = make_float4(pw, v[k].x, v[k].y, v[k].z);
        } else if (r == 2) {
            PREVW(z, k, e_z, pz);
            o = make_float4(pz, pw, v[k].x, v[k].y);
        } else {
            PREVW(z, k, e_z, pz);
            PREVW(y, k, e_y, py);
            o = make_float4(py, pz, pw, v[k].x);
        }
        const int g = g0 + (k << 5);
        if (g < nv) __stcs(out4 + g, o);
    }
#undef PREVW
}

extern "C" void kernel_launch(void* const* d_in, const int* in_sizes, int n_in,
                              void* d_out, int out_size)
{
    const float* x     = (const float*)d_in[0];
    const float* w_row = (const float*)d_in[1];
    const float* w_col = (const float*)d_in[2];

    const int n = in_sizes[0];
    int row_length = 1;
    while ((long long)row_length * row_length < (long long)n) row_length <<= 1;

    const int nv = n >> 2;                    // output float4 count
    const int warps = (nv + 127) >> 7;        // 128 vectors per warp
    const int threads = 1024;
    const int blocks = (warps * 32 + threads - 1) / threads;

    shift_warptile<<<blocks, threads>>>((const float4*)x, x, w_row, w_col,
                                        row_length, n, (float4*)d_out);
}

// round 16
// speedup vs baseline: 1.0176x; 1.0176x over previous
#include <cuda_runtime.h>

#define FULL_MASK 0xffffffffu

// out[j] = x[j - offset] for 0 <= j-offset < n else 0, offset from device scalars.
// Warp tile: 128 consecutive output vectors per warp; thread handles k=0..3 at
// lane-contiguous addresses (full coalescing, MLP=4 front-batched aligned loads).
// Misalignment r = offset & 3 fixed via minimal warp shuffles of the needed
// prev-vector words. n % 4 == 0 so whole-vector zero predication is exact.
//
// FINAL configuration (session-best, 81.47us dur / 74.75us kernel / 81.5% DRAM):
// threads=512 is the measured block-size optimum (256: 80.9% DRAM, 512: 81.5%,
// 1024: 75.1% — residency quantization). Kernel time = GB300 mixed read+write
// HBM/LTS ceiling (~7.1 TB/s actual bytes), confirmed path-independent across
// guarded-LDG, MLP=8, persistent double-buffer, TMA-bulk, and copy-engine
// variants.

__global__ void __launch_bounds__(512)
shift_warptile(const float4* __restrict__ x4,
               const float*  __restrict__ xs,
               const float*  __restrict__ w_row,
               const float*  __restrict__ w_col,
               int row_length, int n,
               float4* __restrict__ out4)
{
    const int nv = n >> 2;
    const int offset = (int)(w_row[0] + (float)row_length * w_col[0]);
    const int r = offset & 3;
    const int m = (offset - r) >> 2;          // floor(offset/4)

    const int warp_id = (blockIdx.x * blockDim.x + threadIdx.x) >> 5;
    const int lane    = threadIdx.x & 31;
    const int wbase   = warp_id << 7;         // 128 vectors per warp

    // Front-batched independent aligned loads (MLP = 4).
    float4 v[4];
    int g0 = wbase + lane;
#pragma unroll
    for (int k = 0; k < 4; k++) {
        const int g  = g0 + (k << 5);
        const int sv = g - m;
        float4 t = make_float4(0.f, 0.f, 0.f, 0.f);
        if (g < nv && sv >= 0 && sv < nv) t = __ldcs(x4 + sv);
        v[k] = t;
    }

    if (r == 0) {
#pragma unroll
        for (int k = 0; k < 4; k++) {
            const int g = g0 + (k << 5);
            if (g < nv) __stcs(out4 + g, v[k]);
        }
        return;
    }

    // Extra boundary words for lane 0, k = 0: words (4-r..3) of vector wbase-m-1.
    float e_y = 0.f, e_z = 0.f, e_w = 0.f;
    if (lane == 0) {
        const int ebase = 4 * (wbase - m) - 4;
        if (r >= 3) { int i = ebase + 1; if (i >= 0 && i < n) e_y = __ldcs(xs + i); }
        if (r >= 2) { int i = ebase + 2; if (i >= 0 && i < n) e_z = __ldcs(xs + i); }
        /* r>=1 */ { int i = ebase + 3; if (i >= 0 && i < n) e_w = __ldcs(xs + i); }
    }

    // prev-word fetch: value of component from vector (g-m-1) =
    //   lane>0 : lane-1's v[k];  lane0,k>0 : lane31's v[k-1];  lane0,k0 : e_*
#define PREVW(comp, k, evar, dst)                                              \
    do {                                                                       \
        float _up  = __shfl_up_sync(FULL_MASK, v[k].comp, 1);                  \
        float _b31 = __shfl_sync(FULL_MASK, (k) > 0 ? v[(k)>0?(k)-1:0].comp    \
                                                    : 0.f, 31);                \
        dst = (lane == 0) ? ((k) > 0 ? _b31 : (evar)) : _up;                   \
    } while (0)

#pragma unroll
    for (int k = 0; k < 4; k++) {
        float pw, pz, py;
        PREVW(w, k, e_w, pw);
        float4 o;
        if (r == 1) {
            o = make_float4(pw, v[k].x, v[k].y, v[k].z);
        } else if (r == 2) {
            PREVW(z, k, e_z, pz);
            o = make_float4(pz, pw, v[k].x, v[k].y);
        } else {
            PREVW(z, k, e_z, pz);
            PREVW(y, k, e_y, py);
            o = make_float4(py, pz, pw, v[k].x);
        }
        const int g = g0 + (k << 5);
        if (g < nv) __stcs(out4 + g, o);
    }
#undef PREVW
}

extern "C" void kernel_launch(void* const* d_in, const int* in_sizes, int n_in,
                              void* d_out, int out_size)
{
    const float* x     = (const float*)d_in[0];
    const float* w_row = (const float*)d_in[1];
    const float* w_col = (const float*)d_in[2];

    const int n = in_sizes[0];
    int row_length = 1;
    while ((long long)row_length * row_length < (long long)n) row_length <<= 1;

    const int nv = n >> 2;                    // output float4 count
    const int warps = (nv + 127) >> 7;        // 128 vectors per warp
    const int threads = 512;
    const int blocks = (warps * 32 + threads - 1) / threads;

    shift_warptile<<<blocks, threads>>>((const float4*)x, x, w_row, w_col,
                                        row_length, n, (float4*)d_out);
}